// round 11
// baseline (speedup 1.0000x reference)
#include <cuda_runtime.h>
#include <math.h>
#include <stdint.h>

#define NN   30000
#define FF   500
#define HID  16
#define OUTC 3
#define EE   960000

#define NGRP  64             // group-pairs per slot (groups s and s+64)
#define JP    1024           // su j-plane stride in ull (16*64)
#define PROW  275            // sh1p padded row stride in ull (258 + 258/16 + slack)

typedef unsigned long long ull;

// ---------------- packed f32x2 helpers ----------------
__device__ __forceinline__ ull pk2(float lo, float hi) {
    ull r; asm("mov.b64 %0, {%1,%2};" : "=l"(r) : "f"(lo), "f"(hi)); return r;
}
__device__ __forceinline__ void upk2(ull v, float& lo, float& hi) {
    asm("mov.b64 {%0,%1}, %2;" : "=f"(lo), "=f"(hi) : "l"(v));
}
__device__ __forceinline__ ull fma2(ull a, ull b, ull c) {
    ull d; asm("fma.rn.f32x2 %0, %1, %2, %3;" : "=l"(d) : "l"(a), "l"(b), "l"(c)); return d;
}
__device__ __forceinline__ void red_add_v4(float* p, float a, float b, float c, float d) {
    asm volatile("red.global.add.v4.f32 [%0], {%1,%2,%3,%4};"
                 :: "l"(p), "f"(a), "f"(b), "f"(c), "f"(d) : "memory");
}

// bank-spread swizzle for stride-4 LDS.64 windows
__device__ __forceinline__ int physu(int u) { return u + (u >> 4); }

// ---------------- scratch ----------------
__device__ float g_hfeat[NN * HID];
__device__ float g_deg[NN];
__device__ float g_dinv[NN];
__device__ float g_t1[NN * HID];
__device__ float g_agg1[NN * HID];
__device__ float g_t2[NN * 4];
__device__ float g_agg2[NN * 4];

// ---------------- dynamic smem layout (byte offsets) ----------------
#define SM_SH1P  0                         // 4 x PROW ull           =  8800 B
#define SM_SU    (SM_SH1P + 4*PROW*8)      // 6 x 16 x 64 ull        = 49152 B
#define SM_SGW   (SM_SU + 6*JP*8)          // 16 x 16 x 6 ull (dup)  = 12288 B
#define SM_SX    (SM_SGW + 16*16*6*8)      // 503 floats             =  2012 B
#define SM_BYTES (SM_SX + 503*4 + 16)
#define DYN_SMEM SM_BYTES

// ================= fused conv1 -> relu -> Winograd F(4,3) conv2 -> relu -> maxpool =================
// 256 threads / block. Chunked over input channels (4 per chunk).
__global__ void __launch_bounds__(256) conv_wino_kernel(
    const float* __restrict__ x,
    const float* __restrict__ w1, const float* __restrict__ b1,
    const float* __restrict__ w2, const float* __restrict__ b2)
{
    extern __shared__ __align__(16) char smem[];
    ull*   sh1p = (ull*)  (smem + SM_SH1P);      // [4][PROW]  packed (val[u], val[u+256])
    ull*   su   = (ull*)  (smem + SM_SU);        // [6][16][64] component-major
    ull*   sgw  = (ull*)  (smem + SM_SGW);       // [16][16][6] dup-pairs
    float* sx   = (float*)(smem + SM_SX);        // [503]; sx[k] = x[k-1], zero pads
    __shared__ float sw1[HID * 3];
    __shared__ float sb1[HID];
    __shared__ float sred[8][4];

    const int node = blockIdx.x;
    const int t = threadIdx.x;
    const int warp = t >> 5;
    const int lane = t & 31;

    if (t == 0) g_deg[node] = 1.0f;              // fused self-loop deg init

    // ---- phase 0: stage x, w1/b1, transform conv2 weights ----
    {
        const float* xr = x + (size_t)node * FF;
        for (int p = t; p < FF; p += 256) sx[p + 1] = xr[p];
        if (t == 0) { sx[0] = 0.f; sx[501] = 0.f; sx[502] = 0.f; }
        if (t < HID * 3) sw1[t] = w1[t];
        if (t < HID) sb1[t] = b1[t];
        int o = t >> 4;
        int i = t & 15;
        float v0 = w2[(o * HID + i) * 3 + 0];
        float v1 = w2[(o * HID + i) * 3 + 1];
        float v2 = w2[(o * HID + i) * 3 + 2];
        float g0 = 0.25f * v0;
        float g1 = (-1.f / 6.f) * (v0 + v1 + v2);
        float g2 = (-1.f / 6.f) * (v0 - v1 + v2);
        float g3 = (1.f / 24.f) * (v0 + 2.f * v1 + 4.f * v2);
        float g4 = (1.f / 24.f) * (v0 - 2.f * v1 + 4.f * v2);
        float g5 = v2;
        ull* dst = &sgw[(i * HID + o) * 6];
        dst[0] = pk2(g0, g0); dst[1] = pk2(g1, g1); dst[2] = pk2(g2, g2);
        dst[3] = pk2(g3, g3); dst[4] = pk2(g4, g4); dst[5] = pk2(g5, g5);
    }
    __syncthreads();

    // ---- chunked phases A (conv1 -> packed sh1p) and B (input transform -> su) ----
    const ull c4  = pk2(4.f, 4.f);
    const ull cm4 = pk2(-4.f, -4.f);
    const ull cm5 = pk2(-5.f, -5.f);
    const ull c2  = pk2(2.f, 2.f);
    const ull cm2 = pk2(-2.f, -2.f);
    const ull c1  = pk2(1.f, 1.f);
    const ull cm1 = pk2(-1.f, -1.f);

    for (int chunk = 0; chunk < 4; chunk++) {
        // phase A: fill sh1p[i_loc][phys(u)] = (val(i,u), val(i,u+256)), u in [0,258)
        for (int idx = t; idx < 4 * 258; idx += 256) {
            int i_loc = idx / 258;
            int u = idx - i_loc * 258;
            int i = chunk * 4 + i_loc;
            float wa = sw1[i * 3 + 0], wb = sw1[i * 3 + 1], wc = sw1[i * 3 + 2];
            float bi = sb1[i];
            float lo = 0.f, hi = 0.f;
            if (u >= 1 && u <= 500)
                lo = fmaxf(bi + wa * sx[u - 1] + wb * sx[u] + wc * sx[u + 1], 0.f);
            int u2 = u + 256;
            if (u2 <= 500)
                hi = fmaxf(bi + wa * sx[u2 - 1] + wb * sx[u2] + wc * sx[u2 + 1], 0.f);
            sh1p[i_loc * PROW + physu(u)] = pk2(lo, hi);
        }
        __syncthreads();

        // phase B: one group-pair per thread: i_loc = t>>6, s = t&63
        {
            int i_loc = t >> 6;
            int s = t & 63;
            int i = chunk * 4 + i_loc;
            const ull* r = &sh1p[i_loc * PROW];
            ull d[6];
#pragma unroll
            for (int j = 0; j < 6; j++) d[j] = r[physu(4 * s + j)];
            ull s31 = fma2(cm1, d[1], d[3]);
            ull s42 = fma2(cm1, d[2], d[4]);
            ull s12 = fma2(cm1, d[2], d[1]);
            ull s43 = fma2(cm1, d[3], d[4]);
            ull a12 = fma2(c1, d[1], d[2]);
            ull a34 = fma2(c1, d[3], d[4]);
            int base = i * NGRP + s;
            su[0 * JP + base] = fma2(cm5, d[2], fma2(c4, d[0], d[4]));
            su[1 * JP + base] = fma2(cm4, a12, a34);
            su[2 * JP + base] = fma2(c4, s12, s43);
            su[3 * JP + base] = fma2(c2, s31, s42);
            su[4 * JP + base] = fma2(cm2, s31, s42);
            su[5 * JP + base] = fma2(cm5, d[3], fma2(c4, d[1], d[5]));
        }
        __syncthreads();
    }

    // ---- phase C: elementwise-product accumulation ----
    const int og = t >> 6;
    const int s = t & 63;
    ull acc[4][6];
#pragma unroll
    for (int o = 0; o < 4; o++)
#pragma unroll
        for (int j = 0; j < 6; j++) acc[o][j] = 0ull;

    for (int i = 0; i < HID; i++) {
        int base = i * NGRP + s;
        ull U[6];
#pragma unroll
        for (int j = 0; j < 6; j++) U[j] = su[j * JP + base];   // conflict-free LDS.64
#pragma unroll
        for (int o = 0; o < 4; o++) {
            const ulonglong2* gp = (const ulonglong2*)&sgw[(i * HID + og * 4 + o) * 6];
            ulonglong2 g01 = gp[0], g23 = gp[1], g45 = gp[2];   // warp-uniform broadcast
            acc[o][0] = fma2(g01.x, U[0], acc[o][0]);
            acc[o][1] = fma2(g01.y, U[1], acc[o][1]);
            acc[o][2] = fma2(g23.x, U[2], acc[o][2]);
            acc[o][3] = fma2(g23.y, U[3], acc[o][3]);
            acc[o][4] = fma2(g45.x, U[4], acc[o][4]);
            acc[o][5] = fma2(g45.y, U[5], acc[o][5]);
        }
    }

    // ---- phase D: output transform A^T m + bias + relu + max ----
    float chmax[4] = { 0.f, 0.f, 0.f, 0.f };
    const bool hi_valid = (s <= 60);              // group s+64 valid iff <= 124
#pragma unroll
    for (int o = 0; o < 4; o++) {
        float bias = b2[og * 4 + o];
        float mlo[6], mhi[6];
#pragma unroll
        for (int j = 0; j < 6; j++) upk2(acc[o][j], mlo[j], mhi[j]);
        {
            float t1 = mlo[1] + mlo[2], t2 = mlo[1] - mlo[2];
            float t3 = mlo[3] + mlo[4], t4 = mlo[3] - mlo[4];
            float y0 = mlo[0] + t1 + t3 + bias;
            float y1 = t2 + 2.f * t4 + bias;
            float y2 = t1 + 4.f * t3 + bias;
            float y3 = t2 + 8.f * t4 + mlo[5] + bias;
            chmax[o] = fmaxf(chmax[o], fmaxf(fmaxf(y0, y1), fmaxf(y2, y3)));
        }
        if (hi_valid) {
            float t1 = mhi[1] + mhi[2], t2 = mhi[1] - mhi[2];
            float t3 = mhi[3] + mhi[4], t4 = mhi[3] - mhi[4];
            float y0 = mhi[0] + t1 + t3 + bias;
            float y1 = t2 + 2.f * t4 + bias;
            float y2 = t1 + 4.f * t3 + bias;
            float y3 = t2 + 8.f * t4 + mhi[5] + bias;
            chmax[o] = fmaxf(chmax[o], fmaxf(fmaxf(y0, y1), fmaxf(y2, y3)));
        }
    }

#pragma unroll
    for (int o = 0; o < 4; o++) {
#pragma unroll
        for (int sh = 16; sh > 0; sh >>= 1)
            chmax[o] = fmaxf(chmax[o], __shfl_xor_sync(0xFFFFFFFFu, chmax[o], sh));
    }
    if (lane == 0) {
#pragma unroll
        for (int o = 0; o < 4; o++) sred[warp][o] = chmax[o];
    }
    __syncthreads();
    if (t < HID) {
        int oq = t >> 2;
        int o = t & 3;
        g_hfeat[node * HID + t] = fmaxf(sred[oq * 2][o], sred[oq * 2 + 1][o]);
    }
}

// ================= GCN kernels =================
__global__ void count_deg_kernel(const int* __restrict__ ei) {
    int e = blockIdx.x * blockDim.x + threadIdx.x;
    if (e < EE) atomicAdd(&g_deg[ei[EE + e]], 1.0f);
}

__global__ void gcn1_lin_kernel(const float* __restrict__ w) {
    int gid = blockIdx.x * blockDim.x + threadIdx.x;
    if (gid >= NN * HID) return;
    int n = gid >> 4;
    int o = gid & 15;
    float di = rsqrtf(g_deg[n]);
    if (o == 0) g_dinv[n] = di;
    const float* h = g_hfeat + n * HID;
    float s = 0.f;
#pragma unroll
    for (int i = 0; i < HID; i++) s = fmaf(h[i], w[i * HID + o], s);
    g_t1[gid] = s;
    g_agg1[gid] = s * di * di;
}

__global__ void scatter1_kernel(const int* __restrict__ ei) {
    int e = blockIdx.x * blockDim.x + threadIdx.x;
    if (e >= EE) return;
    int s = ei[e];
    int d = ei[EE + e];
    float norm = g_dinv[s] * g_dinv[d];
    const float4* ts = (const float4*)(g_t1 + s * HID);
    float* out = g_agg1 + d * HID;
#pragma unroll
    for (int q = 0; q < 4; q++) {
        float4 v = ts[q];
        red_add_v4(out + q * 4, v.x * norm, v.y * norm, v.z * norm, v.w * norm);
    }
}

__global__ void gcn2_lin_kernel(const float* __restrict__ b1,
                                const float* __restrict__ w2g) {
    int n = blockIdx.x * blockDim.x + threadIdx.x;
    if (n >= NN) return;
    float hg[HID];
#pragma unroll
    for (int o = 0; o < HID; o++)
        hg[o] = fmaxf(g_agg1[n * HID + o] + b1[o], 0.f);
    float di = g_dinv[n];
    float d2 = di * di;
#pragma unroll
    for (int j = 0; j < OUTC; j++) {
        float s = 0.f;
#pragma unroll
        for (int o = 0; o < HID; o++) s = fmaf(hg[o], w2g[o * OUTC + j], s);
        g_t2[n * 4 + j] = s;
        g_agg2[n * 4 + j] = s * d2;
    }
    g_t2[n * 4 + 3] = 0.f;
    g_agg2[n * 4 + 3] = 0.f;
}

__global__ void scatter2_kernel(const int* __restrict__ ei) {
    int e = blockIdx.x * blockDim.x + threadIdx.x;
    if (e >= EE) return;
    int s = ei[e];
    int d = ei[EE + e];
    float norm = g_dinv[s] * g_dinv[d];
    float4 v = *(const float4*)(g_t2 + s * 4);
    red_add_v4(g_agg2 + d * 4, v.x * norm, v.y * norm, v.z * norm, 0.f);
}

__global__ void final_kernel(const float* __restrict__ b2g,
                             float* __restrict__ out) {
    int n = blockIdx.x * blockDim.x + threadIdx.x;
    if (n >= NN) return;
    float v0 = g_agg2[n * 4 + 0] + b2g[0];
    float v1 = g_agg2[n * 4 + 1] + b2g[1];
    float v2 = g_agg2[n * 4 + 2] + b2g[2];
    float m = fmaxf(v0, fmaxf(v1, v2));
    float z = m + logf(expf(v0 - m) + expf(v1 - m) + expf(v2 - m));
    out[n * 3 + 0] = v0 - z;
    out[n * 3 + 1] = v1 - z;
    out[n * 3 + 2] = v2 - z;
}

// ================= launch =================
extern "C" void kernel_launch(void* const* d_in, const int* in_sizes, int n_in,
                              void* d_out, int out_size)
{
    const float* x   = (const float*)d_in[0];
    const float* c1w = (const float*)d_in[1];
    const float* c1b = (const float*)d_in[2];
    const float* c2w = (const float*)d_in[3];
    const float* c2b = (const float*)d_in[4];
    const float* g1w = (const float*)d_in[5];
    const float* g1b = (const float*)d_in[6];
    const float* g2w = (const float*)d_in[7];
    const float* g2b = (const float*)d_in[8];
    const int*   ei  = (const int*)d_in[9];
    float* out = (float*)d_out;

    static int smem_set = 0;
    if (!smem_set) {
        cudaFuncSetAttribute(conv_wino_kernel,
                             cudaFuncAttributeMaxDynamicSharedMemorySize, DYN_SMEM);
        smem_set = 1;
    }

    conv_wino_kernel<<<NN, 256, DYN_SMEM>>>(x, c1w, c1b, c2w, c2b);

    count_deg_kernel<<<(EE + 255) / 256, 256>>>(ei);

    gcn1_lin_kernel<<<(NN * HID + 127) / 128, 128>>>(g1w);
    scatter1_kernel<<<(EE + 255) / 256, 256>>>(ei);

    gcn2_lin_kernel<<<(NN + 255) / 256, 256>>>(g1b, g2w);
    scatter2_kernel<<<(EE + 255) / 256, 256>>>(ei);

    final_kernel<<<(NN + 255) / 256, 256>>>(g2b, out);
}

// round 12
// speedup vs baseline: 1.3055x; 1.3055x over previous
#include <cuda_runtime.h>
#include <math.h>
#include <stdint.h>

#define NN   30000
#define FF   500
#define HID  16
#define OUTC 3
#define EE   960000

#define NGRP  64             // group-pair columns (s pairs with s+64); 125 real groups
#define JP    1024           // su j-plane stride in ull (16*64)

typedef unsigned long long ull;

// ---------------- packed f32x2 helpers ----------------
__device__ __forceinline__ ull pk2(float lo, float hi) {
    ull r; asm("mov.b64 %0, {%1,%2};" : "=l"(r) : "f"(lo), "f"(hi)); return r;
}
__device__ __forceinline__ void upk2(ull v, float& lo, float& hi) {
    asm("mov.b64 {%0,%1}, %2;" : "=f"(lo), "=f"(hi) : "l"(v));
}
__device__ __forceinline__ ull fma2(ull a, ull b, ull c) {
    ull d; asm("fma.rn.f32x2 %0, %1, %2, %3;" : "=l"(d) : "l"(a), "l"(b), "l"(c)); return d;
}
__device__ __forceinline__ void red_add_v4(float* p, float a, float b, float c, float d) {
    asm volatile("red.global.add.v4.f32 [%0], {%1,%2,%3,%4};"
                 :: "l"(p), "f"(a), "f"(b), "f"(c), "f"(d) : "memory");
}

// ---------------- scratch ----------------
__device__ float g_hfeat[NN * HID];
__device__ float g_deg[NN];
__device__ float g_dinv[NN];
__device__ float g_t1[NN * HID];
__device__ float g_agg1[NN * HID];
__device__ float g_t2[NN * 4];
__device__ float g_agg2[NN * 4];

// ---------------- dynamic smem layout (byte offsets) ----------------
#define SM_SU    0                         // 6 x 16 x 64 ull        = 49152 B
#define SM_SGW   (SM_SU + 6*JP*8)          // 16 x 16 x 6 ull (dup)  = 12288 B
#define SM_SXV   (SM_SGW + 16*16*6*8)      // 520 floats, zero-padded=  2080 B
#define SM_BYTES (SM_SXV + 520*4 + 16)
#define DYN_SMEM SM_BYTES

// ================= fused conv1 -> relu -> Winograd F(4,3) conv2 -> relu -> maxpool =================
// 256 threads / block, one block per node. 3 barriers total.
__global__ void __launch_bounds__(256) conv_wino_kernel(
    const float* __restrict__ x,
    const float* __restrict__ w1, const float* __restrict__ b1,
    const float* __restrict__ w2, const float* __restrict__ b2)
{
    extern __shared__ __align__(16) char smem[];
    ull*   su  = (ull*)  (smem + SM_SU);         // [6][16][64] component-major
    ull*   sgw = (ull*)  (smem + SM_SGW);        // [16][16][6] dup-pairs
    float* sxv = (float*)(smem + SM_SXV);        // sxv[k] = x[k-1] for 1<=k<=500, else 0; k in [0,520)
    __shared__ float sw1[HID * 3];
    __shared__ float sb1[HID];
    __shared__ float sred[8][4];

    const int node = blockIdx.x;
    const int t = threadIdx.x;
    const int warp = t >> 5;
    const int lane = t & 31;

    if (t == 0) g_deg[node] = 1.0f;              // fused self-loop deg init

    // ---- phase 0: stage sxv, w1/b1, transformed conv2 weights ----
    {
        const float* xr = x + (size_t)node * FF;
        for (int k = t; k < 520; k += 256)
            sxv[k] = (k >= 1 && k <= FF) ? xr[k - 1] : 0.f;
        if (t < HID * 3) sw1[t] = w1[t];
        if (t < HID) sb1[t] = b1[t];
        int o = t >> 4;
        int i = t & 15;
        float v0 = w2[(o * HID + i) * 3 + 0];
        float v1 = w2[(o * HID + i) * 3 + 1];
        float v2 = w2[(o * HID + i) * 3 + 2];
        float g0 = 0.25f * v0;
        float g1 = (-1.f / 6.f) * (v0 + v1 + v2);
        float g2 = (-1.f / 6.f) * (v0 - v1 + v2);
        float g3 = (1.f / 24.f) * (v0 + 2.f * v1 + 4.f * v2);
        float g4 = (1.f / 24.f) * (v0 - 2.f * v1 + 4.f * v2);
        float g5 = v2;
        ull* dst = &sgw[(i * HID + o) * 6];
        dst[0] = pk2(g0, g0); dst[1] = pk2(g1, g1); dst[2] = pk2(g2, g2);
        dst[3] = pk2(g3, g3); dst[4] = pk2(g4, g4); dst[5] = pk2(g5, g5);
    }
    __syncthreads();

    // ---- phase B': fused conv1 + input transform, 4 slots per thread ----
    {
        const ull c4  = pk2(4.f, 4.f);
        const ull cm4 = pk2(-4.f, -4.f);
        const ull cm5 = pk2(-5.f, -5.f);
        const ull c2  = pk2(2.f, 2.f);
        const ull cm2 = pk2(-2.f, -2.f);
        const ull c1  = pk2(1.f, 1.f);
        const ull cm1 = pk2(-1.f, -1.f);
#pragma unroll
        for (int slot = 0; slot < 4; slot++) {
            int idx = slot * 256 + t;
            int i = idx >> 6;                    // uniform within warp
            int s = idx & 63;
            float wa = sw1[i * 3 + 0], wb = sw1[i * 3 + 1], wc = sw1[i * 3 + 2];
            float bi = sb1[i];
            // conv1 on the fly: h(p) = relu(bi + wa*x[p-1] + wb*x[p] + wc*x[p+1])
            //   x[p-1] = sxv[p], x[p] = sxv[p+1], x[p+1] = sxv[p+2]
            // windows: col0 p = 4s-1+j, col1 p = 4s+255+j (j = 0..5)
            float h0[6], h1v[6];
            int p0b = 4 * s - 1;
            int p1b = 4 * s + 255;
#pragma unroll
            for (int j = 0; j < 6; j++) {
                int p0 = p0b + j;
                // sxv index p0 >= -1: sxv[-1] never read because guard kills p0=-1 path;
                // use max(p0,0) to keep the load safe.
                int q0 = p0 < 0 ? 0 : p0;
                float v = bi + wa * sxv[q0] + wb * sxv[q0 + 1] + wc * sxv[q0 + 2];
                h0[j] = (p0 >= 0 && p0 < FF) ? fmaxf(v, 0.f) : 0.f;
                int p1 = p1b + j;
                float u = bi + wa * sxv[p1] + wb * sxv[p1 + 1] + wc * sxv[p1 + 2];
                h1v[j] = (p1 < FF) ? fmaxf(u, 0.f) : 0.f;
            }
            ull d[6];
#pragma unroll
            for (int j = 0; j < 6; j++) d[j] = pk2(h0[j], h1v[j]);
            ull s31 = fma2(cm1, d[1], d[3]);
            ull s42 = fma2(cm1, d[2], d[4]);
            ull s12 = fma2(cm1, d[2], d[1]);
            ull s43 = fma2(cm1, d[3], d[4]);
            ull a12 = fma2(c1, d[1], d[2]);
            ull a34 = fma2(c1, d[3], d[4]);
            int base = i * NGRP + s;
            su[0 * JP + base] = fma2(cm5, d[2], fma2(c4, d[0], d[4]));
            su[1 * JP + base] = fma2(cm4, a12, a34);
            su[2 * JP + base] = fma2(c4, s12, s43);
            su[3 * JP + base] = fma2(c2, s31, s42);
            su[4 * JP + base] = fma2(cm2, s31, s42);
            su[5 * JP + base] = fma2(cm5, d[3], fma2(c4, d[1], d[5]));
        }
    }
    __syncthreads();

    // ---- phase C: elementwise-product accumulation ----
    const int og = t >> 6;
    const int s = t & 63;
    ull acc[4][6];
#pragma unroll
    for (int o = 0; o < 4; o++)
#pragma unroll
        for (int j = 0; j < 6; j++) acc[o][j] = 0ull;

    for (int i = 0; i < HID; i++) {
        int base = i * NGRP + s;
        ull U[6];
#pragma unroll
        for (int j = 0; j < 6; j++) U[j] = su[j * JP + base];   // conflict-free LDS.64
#pragma unroll
        for (int o = 0; o < 4; o++) {
            const ulonglong2* gp = (const ulonglong2*)&sgw[(i * HID + og * 4 + o) * 6];
            ulonglong2 g01 = gp[0], g23 = gp[1], g45 = gp[2];   // warp-uniform broadcast
            acc[o][0] = fma2(g01.x, U[0], acc[o][0]);
            acc[o][1] = fma2(g01.y, U[1], acc[o][1]);
            acc[o][2] = fma2(g23.x, U[2], acc[o][2]);
            acc[o][3] = fma2(g23.y, U[3], acc[o][3]);
            acc[o][4] = fma2(g45.x, U[4], acc[o][4]);
            acc[o][5] = fma2(g45.y, U[5], acc[o][5]);
        }
    }

    // ---- phase D: output transform A^T m + bias + relu + max ----
    float chmax[4] = { 0.f, 0.f, 0.f, 0.f };
    const bool hi_valid = (s <= 60);              // group s+64 valid iff index <= 124
#pragma unroll
    for (int o = 0; o < 4; o++) {
        float bias = b2[og * 4 + o];
        float mlo[6], mhi[6];
#pragma unroll
        for (int j = 0; j < 6; j++) upk2(acc[o][j], mlo[j], mhi[j]);
        {
            float t1 = mlo[1] + mlo[2], t2 = mlo[1] - mlo[2];
            float t3 = mlo[3] + mlo[4], t4 = mlo[3] - mlo[4];
            float y0 = mlo[0] + t1 + t3 + bias;
            float y1 = t2 + 2.f * t4 + bias;
            float y2 = t1 + 4.f * t3 + bias;
            float y3 = t2 + 8.f * t4 + mlo[5] + bias;
            chmax[o] = fmaxf(chmax[o], fmaxf(fmaxf(y0, y1), fmaxf(y2, y3)));
        }
        if (hi_valid) {
            float t1 = mhi[1] + mhi[2], t2 = mhi[1] - mhi[2];
            float t3 = mhi[3] + mhi[4], t4 = mhi[3] - mhi[4];
            float y0 = mhi[0] + t1 + t3 + bias;
            float y1 = t2 + 2.f * t4 + bias;
            float y2 = t1 + 4.f * t3 + bias;
            float y3 = t2 + 8.f * t4 + mhi[5] + bias;
            chmax[o] = fmaxf(chmax[o], fmaxf(fmaxf(y0, y1), fmaxf(y2, y3)));
        }
    }

#pragma unroll
    for (int o = 0; o < 4; o++) {
#pragma unroll
        for (int sh = 16; sh > 0; sh >>= 1)
            chmax[o] = fmaxf(chmax[o], __shfl_xor_sync(0xFFFFFFFFu, chmax[o], sh));
    }
    if (lane == 0) {
#pragma unroll
        for (int o = 0; o < 4; o++) sred[warp][o] = chmax[o];
    }
    __syncthreads();
    if (t < HID) {
        int oq = t >> 2;
        int o = t & 3;
        g_hfeat[node * HID + t] = fmaxf(sred[oq * 2][o], sred[oq * 2 + 1][o]);
    }
}

// ================= GCN kernels =================
__global__ void count_deg_kernel(const int* __restrict__ ei) {
    int e = blockIdx.x * blockDim.x + threadIdx.x;
    if (e < EE) atomicAdd(&g_deg[ei[EE + e]], 1.0f);
}

__global__ void gcn1_lin_kernel(const float* __restrict__ w) {
    int gid = blockIdx.x * blockDim.x + threadIdx.x;
    if (gid >= NN * HID) return;
    int n = gid >> 4;
    int o = gid & 15;
    float di = rsqrtf(g_deg[n]);
    if (o == 0) g_dinv[n] = di;
    const float* h = g_hfeat + n * HID;
    float s = 0.f;
#pragma unroll
    for (int i = 0; i < HID; i++) s = fmaf(h[i], w[i * HID + o], s);
    g_t1[gid] = s;
    g_agg1[gid] = s * di * di;
}

__global__ void scatter1_kernel(const int* __restrict__ ei) {
    int e = blockIdx.x * blockDim.x + threadIdx.x;
    if (e >= EE) return;
    int s = ei[e];
    int d = ei[EE + e];
    float norm = g_dinv[s] * g_dinv[d];
    const float4* ts = (const float4*)(g_t1 + s * HID);
    float* out = g_agg1 + d * HID;
#pragma unroll
    for (int q = 0; q < 4; q++) {
        float4 v = ts[q];
        red_add_v4(out + q * 4, v.x * norm, v.y * norm, v.z * norm, v.w * norm);
    }
}

__global__ void gcn2_lin_kernel(const float* __restrict__ b1,
                                const float* __restrict__ w2g) {
    int n = blockIdx.x * blockDim.x + threadIdx.x;
    if (n >= NN) return;
    float hg[HID];
#pragma unroll
    for (int o = 0; o < HID; o++)
        hg[o] = fmaxf(g_agg1[n * HID + o] + b1[o], 0.f);
    float di = g_dinv[n];
    float d2 = di * di;
#pragma unroll
    for (int j = 0; j < OUTC; j++) {
        float s = 0.f;
#pragma unroll
        for (int o = 0; o < HID; o++) s = fmaf(hg[o], w2g[o * OUTC + j], s);
        g_t2[n * 4 + j] = s;
        g_agg2[n * 4 + j] = s * d2;
    }
    g_t2[n * 4 + 3] = 0.f;
    g_agg2[n * 4 + 3] = 0.f;
}

__global__ void scatter2_kernel(const int* __restrict__ ei) {
    int e = blockIdx.x * blockDim.x + threadIdx.x;
    if (e >= EE) return;
    int s = ei[e];
    int d = ei[EE + e];
    float norm = g_dinv[s] * g_dinv[d];
    float4 v = *(const float4*)(g_t2 + s * 4);
    red_add_v4(g_agg2 + d * 4, v.x * norm, v.y * norm, v.z * norm, 0.f);
}

__global__ void final_kernel(const float* __restrict__ b2g,
                             float* __restrict__ out) {
    int n = blockIdx.x * blockDim.x + threadIdx.x;
    if (n >= NN) return;
    float v0 = g_agg2[n * 4 + 0] + b2g[0];
    float v1 = g_agg2[n * 4 + 1] + b2g[1];
    float v2 = g_agg2[n * 4 + 2] + b2g[2];
    float m = fmaxf(v0, fmaxf(v1, v2));
    float z = m + logf(expf(v0 - m) + expf(v1 - m) + expf(v2 - m));
    out[n * 3 + 0] = v0 - z;
    out[n * 3 + 1] = v1 - z;
    out[n * 3 + 2] = v2 - z;
}

// ================= launch =================
extern "C" void kernel_launch(void* const* d_in, const int* in_sizes, int n_in,
                              void* d_out, int out_size)
{
    const float* x   = (const float*)d_in[0];
    const float* c1w = (const float*)d_in[1];
    const float* c1b = (const float*)d_in[2];
    const float* c2w = (const float*)d_in[3];
    const float* c2b = (const float*)d_in[4];
    const float* g1w = (const float*)d_in[5];
    const float* g1b = (const float*)d_in[6];
    const float* g2w = (const float*)d_in[7];
    const float* g2b = (const float*)d_in[8];
    const int*   ei  = (const int*)d_in[9];
    float* out = (float*)d_out;

    static int smem_set = 0;
    if (!smem_set) {
        cudaFuncSetAttribute(conv_wino_kernel,
                             cudaFuncAttributeMaxDynamicSharedMemorySize, DYN_SMEM);
        smem_set = 1;
    }

    conv_wino_kernel<<<NN, 256, DYN_SMEM>>>(x, c1w, c1b, c2w, c2b);

    count_deg_kernel<<<(EE + 255) / 256, 256>>>(ei);

    gcn1_lin_kernel<<<(NN * HID + 127) / 128, 128>>>(g1w);
    scatter1_kernel<<<(EE + 255) / 256, 256>>>(ei);

    gcn2_lin_kernel<<<(NN + 255) / 256, 256>>>(g1b, g2w);
    scatter2_kernel<<<(EE + 255) / 256, 256>>>(ei);

    final_kernel<<<(NN + 255) / 256, 256>>>(g2b, out);
}